// round 5
// baseline (speedup 1.0000x reference)
#include <cuda_runtime.h>

#define NR 512
#define DD 768
#define EPSF 1e-8f
#define LN2F 0.69314718055994530942f
#define LAMBDF 1.0f

#define TI 16                // pair tile is 16x16
#define BK 128
#define PADF 132             // 128 + 4 floats -> float4 stride 33 (odd)
#define PAD4 (PADF/4)        // 33
#define NBLK ((NR/TI)*(NR/TI))   // 1024 pair blocks
#define NT 64                // threads per pair block (8x8, each does 2x2 pairs)

// Scratch (no cudaMalloc allowed)
__device__ float    g_P1[NR * DD];   // p1 + eps
__device__ float    g_P2[NR * DD];   // p2 + eps
__device__ float    g_H1[NR];        // sum p1*ln(p1+eps)
__device__ float    g_H2[NR];
__device__ float    g_ptot[NBLK];    // per-block tot partials
__device__ float    g_pdia[NBLK];    // per-block dia partials
__device__ unsigned g_counter = 0;   // ticket for last-block finalize (self-resetting)

// One block per row; blocks [0,512) -> z1, [512,1024) -> z2. 256 threads, 3 elems each.
__global__ void softmax_kernel(const float* __restrict__ z1,
                               const float* __restrict__ z2) {
    const int  row   = blockIdx.x & (NR - 1);
    const bool first = blockIdx.x < NR;
    const float* src = (first ? z1 : z2) + row * DD;
    float*       dst = (first ? g_P1 : g_P2) + row * DD;
    float*      hrow = first ? g_H1 : g_H2;

    const int tid = threadIdx.x;
    const int w = tid >> 5, l = tid & 31;

    float x0 = src[tid];
    float x1 = src[tid + 256];
    float x2 = src[tid + 512];

    __shared__ float sred[8];

    // --- max reduce ---
    float mx = fmaxf(x0, fmaxf(x1, x2));
    #pragma unroll
    for (int o = 16; o; o >>= 1) mx = fmaxf(mx, __shfl_xor_sync(0xffffffffu, mx, o));
    if (l == 0) sred[w] = mx;
    __syncthreads();
    mx = sred[0];
    #pragma unroll
    for (int i = 1; i < 8; i++) mx = fmaxf(mx, sred[i]);
    __syncthreads();

    // --- exp + sum reduce ---
    float e0 = __expf(x0 - mx), e1 = __expf(x1 - mx), e2 = __expf(x2 - mx);
    float s = e0 + e1 + e2;
    #pragma unroll
    for (int o = 16; o; o >>= 1) s += __shfl_xor_sync(0xffffffffu, s, o);
    if (l == 0) sred[w] = s;
    __syncthreads();
    s = sred[0];
    #pragma unroll
    for (int i = 1; i < 8; i++) s += sred[i];
    __syncthreads();

    const float inv = 1.0f / s;
    float p0 = e0 * inv, p1 = e1 * inv, p2 = e2 * inv;
    float a0 = p0 + EPSF, a1 = p1 + EPSF, a2 = p2 + EPSF;
    dst[tid]       = a0;
    dst[tid + 256] = a1;
    dst[tid + 512] = a2;

    // --- H = sum p * ln(p+eps) ---
    float h = p0 * __log2f(a0) + p1 * __log2f(a1) + p2 * __log2f(a2);
    #pragma unroll
    for (int o = 16; o; o >>= 1) h += __shfl_xor_sync(0xffffffffu, h, o);
    if (l == 0) sred[w] = h;
    __syncthreads();
    if (tid == 0) {
        float hs = 0.f;
        #pragma unroll
        for (int i = 0; i < 8; i++) hs += sred[i];
        hrow[row] = hs * LN2F;
    }
}

// 16x16 pair tile per block, 64 threads (8x8), each thread a 2x2 pair micro-tile.
// Smem reads: 4B per (i,j,k) element (2x reuse each side) -> LDS floor well under
// the MUFU.LG2 floor, which becomes the sole bound.
// C(i,j) = ln2 * (T1 - 2eps*T2 - 2); jsd = 0.5*(H1 + H2 - C).
__global__ void __launch_bounds__(NT) pair_kernel(float* __restrict__ out) {
    __shared__ float As[TI * PADF];
    __shared__ float Bs[TI * PADF];
    __shared__ float rt2[2], rd2[2];
    __shared__ bool  s_last;

    const int tid = threadIdx.x;
    const int ib = blockIdx.x & 31;   // 512/16 = 32 tiles per dim
    const int jb = blockIdx.x >> 5;
    const int ti = tid & 7;           // i rows: ti, ti+8
    const int tj = tid >> 3;          // j rows: tj, tj+8

    const float4* gp1 = (const float4*)(g_P1 + ib * TI * DD);
    const float4* gp2 = (const float4*)(g_P2 + jb * TI * DD);

    float T100 = 0.f, T101 = 0.f, T110 = 0.f, T111 = 0.f;
    float T200 = 0.f, T201 = 0.f, T210 = 0.f, T211 = 0.f;

    #pragma unroll 1
    for (int kb = 0; kb < DD / BK; kb++) {
        // stage 16 x 128 chunk of each matrix: 512 float4 each, 64 threads -> 8 apiece
        #pragma unroll
        for (int r = 0; r < 8; r++) {
            int idx = tid + r * NT;            // 0..511
            int row = idx >> 5;                // /32
            int c   = idx & 31;
            ((float4*)As)[row * PAD4 + c] = gp1[row * (DD / 4) + kb * (BK / 4) + c];
        }
        #pragma unroll
        for (int r = 0; r < 8; r++) {
            int idx = tid + r * NT;
            int row = idx >> 5;
            int c   = idx & 31;
            ((float4*)Bs)[row * PAD4 + c] = gp2[row * (DD / 4) + kb * (BK / 4) + c];
        }
        __syncthreads();

        const float4* a0p = (const float4*)(As + ti * PADF);
        const float4* a1p = (const float4*)(As + (ti + 8) * PADF);
        const float4* b0p = (const float4*)(Bs + tj * PADF);
        const float4* b1p = (const float4*)(Bs + (tj + 8) * PADF);

        #pragma unroll 4
        for (int k = 0; k < BK / 4; k++) {
            float4 a0 = a0p[k], a1 = a1p[k];
            float4 b0 = b0p[k], b1 = b1p[k];

            #define PAIRSTEP(ax, bx)                                        \
            {                                                               \
                float s00 = a0.ax + b0.bx;  float u00 = __log2f(s00);       \
                float s01 = a0.ax + b1.bx;  float u01 = __log2f(s01);       \
                float s10 = a1.ax + b0.bx;  float u10 = __log2f(s10);       \
                float s11 = a1.ax + b1.bx;  float u11 = __log2f(s11);       \
                T100 = fmaf(s00, u00, T100); T200 += u00;                   \
                T101 = fmaf(s01, u01, T101); T201 += u01;                   \
                T110 = fmaf(s10, u10, T110); T210 += u10;                   \
                T111 = fmaf(s11, u11, T111); T211 += u11;                   \
            }
            PAIRSTEP(x, x)
            PAIRSTEP(y, y)
            PAIRSTEP(z, z)
            PAIRSTEP(w, w)
            #undef PAIRSTEP
        }
        __syncthreads();
    }

    const int gi0 = ib * TI + ti,  gi1 = gi0 + 8;
    const int gj0 = jb * TI + tj,  gj1 = gj0 + 8;

    const float h10 = g_H1[gi0], h11 = g_H1[gi1];
    const float h20 = g_H2[gj0], h21 = g_H2[gj1];

    #define JSD(T1v, T2v, hi, hj) \
        (0.5f * ((hi) + (hj) - LN2F * ((T1v) - 2.0f * EPSF * (T2v) - 2.0f)))
    float j00 = JSD(T100, T200, h10, h20);
    float j01 = JSD(T101, T201, h10, h21);
    float j10 = JSD(T110, T210, h11, h20);
    float j11 = JSD(T111, T211, h11, h21);
    #undef JSD

    float t = j00 + j01 + j10 + j11;
    float d = 0.f;
    if (gi0 == gj0) d += j00;
    if (gi0 == gj1) d += j01;
    if (gi1 == gj0) d += j10;
    if (gi1 == gj1) d += j11;

    const int w = tid >> 5, l = tid & 31;
    #pragma unroll
    for (int o = 16; o; o >>= 1) {
        t += __shfl_xor_sync(0xffffffffu, t, o);
        d += __shfl_xor_sync(0xffffffffu, d, o);
    }
    if (l == 0) { rt2[w] = t; rd2[w] = d; }
    __syncthreads();

    // Per-block partial + ticket (canonical threadFenceReduction pattern)
    if (tid == 0) {
        g_ptot[blockIdx.x] = rt2[0] + rt2[1];
        g_pdia[blockIdx.x] = rd2[0] + rd2[1];
        __threadfence();
        unsigned ticket = atomicAdd(&g_counter, 1u);
        s_last = (ticket == (unsigned)(gridDim.x - 1));
    }
    __syncthreads();

    if (s_last) {
        // Last block: reduce all NBLK partials in double precision.
        double dt = 0.0, dd_ = 0.0;
        for (int i = tid; i < NBLK; i += NT) {
            float pt = *(volatile float*)&g_ptot[i];
            float pd = *(volatile float*)&g_pdia[i];
            dt  += (double)pt;
            dd_ += (double)pd;
        }
        #pragma unroll
        for (int o = 16; o; o >>= 1) {
            dt  += __shfl_xor_sync(0xffffffffu, dt, o);
            dd_ += __shfl_xor_sync(0xffffffffu, dd_, o);
        }
        __shared__ double dtot[2], ddia[2];
        if (l == 0) { dtot[w] = dt; ddia[w] = dd_; }
        __syncthreads();
        if (tid == 0) {
            double tot  = dtot[0] + dtot[1];
            double dia_ = ddia[0] + ddia[1];
            double pos = dia_ / (double)NR;
            double neg = -(tot - dia_) / ((double)NR * NR - NR);
            out[0] = (float)(pos + (double)LAMBDF * neg);
            g_counter = 0;   // reset for next graph replay
        }
    }
}

extern "C" void kernel_launch(void* const* d_in, const int* in_sizes, int n_in,
                              void* d_out, int out_size) {
    const float* z1 = (const float*)d_in[0];
    const float* z2 = (const float*)d_in[1];
    float* out = (float*)d_out;

    softmax_kernel<<<2 * NR, 256>>>(z1, z2);
    pair_kernel<<<NBLK, NT>>>(out);
}